// round 4
// baseline (speedup 1.0000x reference)
#include <cuda_runtime.h>
#include <cuda_bf16.h>
#include <cstdint>
#include <math_constants.h>

#define CDIM 256
#define KCODES 8192
#define NROWS 16384
#define NT 128              // codes per chunk
#define MT 128              // rows per CTA
#define NCHUNKS (KCODES / NT)
#define CAP 128             // candidate slots per row
#define MARGIN 1.5e-3f

// ---------------------------------------------------------------------------
// Device globals (allocation-free scratch)
// ---------------------------------------------------------------------------
__device__ __align__(16) __nv_bfloat16 g_Abf[(size_t)NROWS * CDIM];   // [n][c]
__device__ __align__(16) __nv_bfloat16 g_Bbf[(size_t)KCODES * CDIM];  // [k][c]
__device__ float    g_A[NROWS];                          // exact ||x||^2 (strict seq)
__device__ float    g_C[KCODES];                         // exact ||e||^2 (strict seq)
__device__ unsigned g_candk[(size_t)NROWS * CAP];
__device__ float    g_cands[(size_t)NROWS * CAP];
__device__ int      g_cnt[NROWS];
__device__ float    g_thresh[NROWS];
__device__ int      g_idx[NROWS];
__device__ float    g_partial[NROWS / 64];

// ---------------------------------------------------------------------------
// Helpers
// ---------------------------------------------------------------------------
__device__ __forceinline__ uint32_t smem_to_u32(const void* p) {
    uint32_t a;
    asm("{ .reg .u64 t; cvta.to.shared.u64 t, %1; cvt.u32.u64 %0, t; }" : "=r"(a) : "l"(p));
    return a;
}
__device__ __forceinline__ unsigned f2ord(float f) {   // order-preserving float->uint
    unsigned u = __float_as_uint(f);
    return (u & 0x80000000u) ? ~u : (u | 0x80000000u);
}
__device__ __forceinline__ float ord2f(unsigned u) {
    return __uint_as_float((u & 0x80000000u) ? (u ^ 0x80000000u) : ~u);
}
__device__ __forceinline__ void ldsm4(uint32_t r[4], uint32_t addr) {
    asm volatile("ldmatrix.sync.aligned.m8n8.x4.shared.b16 {%0,%1,%2,%3}, [%4];"
                 : "=r"(r[0]), "=r"(r[1]), "=r"(r[2]), "=r"(r[3]) : "r"(addr));
}
__device__ __forceinline__ void mma16816(float d[4], const uint32_t a[4],
                                         uint32_t b0, uint32_t b1) {
    asm("mma.sync.aligned.m16n8k16.row.col.f32.bf16.bf16.f32 "
        "{%0,%1,%2,%3}, {%4,%5,%6,%7}, {%8,%9}, {%0,%1,%2,%3};"
        : "+f"(d[0]), "+f"(d[1]), "+f"(d[2]), "+f"(d[3])
        : "r"(a[0]), "r"(a[1]), "r"(a[2]), "r"(a[3]), "r"(b0), "r"(b1));
}

// ---------------------------------------------------------------------------
// Prep kernels
// ---------------------------------------------------------------------------
__global__ void conv_a_kernel(const float* __restrict__ z) {   // z[b][c][hw] -> Abf[n][c]
    __shared__ float tile[32][33];
    int b = blockIdx.z, hw0 = blockIdx.x * 32, cb = blockIdx.y * 32;
    int tx = threadIdx.x & 31, ty = threadIdx.x >> 5;
    #pragma unroll
    for (int r = ty; r < 32; r += 8)
        tile[r][tx] = z[((size_t)b * CDIM + cb + r) * 1024 + hw0 + tx];
    __syncthreads();
    #pragma unroll
    for (int r = ty; r < 32; r += 8)
        g_Abf[((size_t)b * 1024 + hw0 + r) * CDIM + cb + tx] = __float2bfloat16_rn(tile[tx][r]);
}

__global__ void conv_b_kernel(const float* __restrict__ emb) {
    int i = blockIdx.x * blockDim.x + threadIdx.x;   // over KCODES*CDIM/4
    float4 v = ((const float4*)emb)[i];
    __nv_bfloat162* dst = (__nv_bfloat162*)g_Bbf;
    dst[i * 2]     = __floats2bfloat162_rn(v.x, v.y);
    dst[i * 2 + 1] = __floats2bfloat162_rn(v.z, v.w);
}

__global__ void c_kernel(const float* __restrict__ emb) {   // strict sequential fp32
    int k = blockIdx.x * blockDim.x + threadIdx.x;
    const float* e = emb + (size_t)k * CDIM;
    float s = 0.f;
    for (int c = 0; c < CDIM; c++) {
        float v = __ldg(e + c);
        s = __fadd_rn(s, __fmul_rn(v, v));
    }
    g_C[k] = s;
}

__global__ void a_kernel(const float* __restrict__ z) {     // strict sequential fp32
    int n = blockIdx.x * blockDim.x + threadIdx.x;
    int b = n >> 10, hw = n & 1023;
    const float* zp = z + (size_t)b * CDIM * 1024 + hw;
    float s = 0.f;
    for (int c = 0; c < CDIM; c++) {
        float v = __ldg(zp + (size_t)c * 1024);
        s = __fadd_rn(s, __fmul_rn(v, v));
    }
    g_A[n] = s;
}

// ---------------------------------------------------------------------------
// GEMM (HMMA mma.sync bf16) + screening
// SMEM layout (bytes): As 0..64K, B0 64K..128K, B1 128K..192K,
//                      C_s 192K (+1KB, 2 x 128 f), runmax (+512), cnt (+512)
// ---------------------------------------------------------------------------
#define SM_A 0
#define SM_B0 65536
#define SM_B1 131072
#define SM_C  196608
#define SM_RMAX (SM_C + 1024)
#define SM_CNT  (SM_RMAX + 512)
#define SM_TOTAL (SM_CNT + 512)

// copy 128 rows x 256 bf16 (64KB) gmem->smem with per-row XOR swizzle
// (16B granule g in row r stored at granule g ^ (r&7); conflict-free LDSM)
__device__ __forceinline__ void st_tile(char* dst, const uint4* __restrict__ src, int tid) {
    #pragma unroll
    for (int it = 0; it < 16; it++) {
        int u = it * 256 + tid;            // 0..4095 uint4
        int row = u >> 5, gr = u & 31;     // 32 granules (512B) per row
        *(uint4*)(dst + row * 512 + ((gr ^ (row & 7)) << 4)) = src[u];
    }
}

__global__ __launch_bounds__(256, 1)
void gemm_screen_kernel() {
    extern __shared__ char smem[];
    const uint32_t smem_base = smem_to_u32(smem);
    const int tid = threadIdx.x;
    const int wid = tid >> 5, lane = tid & 31;
    const int wm = wid >> 1, wn = wid & 1;       // 4x2 warp grid
    const int g = lane >> 2, tg = lane & 3;
    const int n0 = blockIdx.x * MT;

    float*    C_s     = (float*)(smem + SM_C);
    unsigned* sh_rmax = (unsigned*)(smem + SM_RMAX);
    int*      sh_cnt  = (int*)(smem + SM_CNT);

    if (tid < 128) { sh_rmax[tid] = f2ord(-CUDART_INF_F); sh_cnt[tid] = 0; }

    // Prologue: A tile + B chunk 0 + C chunk 0
    st_tile(smem + SM_A, (const uint4*)(g_Abf + (size_t)n0 * CDIM), tid);
    st_tile(smem + SM_B0, (const uint4*)g_Bbf, tid);
    if (tid < 128) C_s[tid] = g_C[tid];
    __syncthreads();

    const uint32_t As_base = smem_base + SM_A;

    for (int i = 0; i < NCHUNKS; i++) {
        const int cur = i & 1, nxt = cur ^ 1;

        // Prefetch next B chunk + C into the other buffer (overlaps with HMMA)
        if (i + 1 < NCHUNKS) {
            st_tile(smem + (nxt ? SM_B1 : SM_B0),
                    (const uint4*)(g_Bbf + (size_t)(i + 1) * NT * CDIM), tid);
            if (tid < 128) C_s[nxt * 128 + tid] = g_C[(i + 1) * NT + tid];
        }

        // ---- compute chunk i ----
        const uint32_t Bs_base = smem_base + (cur ? SM_B1 : SM_B0);
        float acc[2][8][4];
        #pragma unroll
        for (int mt = 0; mt < 2; mt++)
            #pragma unroll
            for (int nt = 0; nt < 8; nt++)
                #pragma unroll
                for (int c = 0; c < 4; c++) acc[mt][nt][c] = 0.f;

        #pragma unroll
        for (int ks = 0; ks < 16; ks++) {
            uint32_t a_frag[2][4];
            #pragma unroll
            for (int mt = 0; mt < 2; mt++) {
                int row = wm * 32 + mt * 16 + (lane & 15);
                int gr  = ks * 2 + (lane >> 4);
                ldsm4(a_frag[mt], As_base + row * 512 + ((gr ^ (row & 7)) << 4));
            }
            uint32_t b_frag[4][4];
            #pragma unroll
            for (int bp = 0; bp < 4; bp++) {
                int n  = wn * 64 + bp * 16 + ((lane >> 4) << 3) + (lane & 7);
                int gr = ks * 2 + ((lane >> 3) & 1);
                ldsm4(b_frag[bp], Bs_base + n * 512 + ((gr ^ (n & 7)) << 4));
            }
            #pragma unroll
            for (int mt = 0; mt < 2; mt++)
                #pragma unroll
                for (int bp = 0; bp < 4; bp++) {
                    mma16816(acc[mt][bp * 2],     a_frag[mt], b_frag[bp][0], b_frag[bp][1]);
                    mma16816(acc[mt][bp * 2 + 1], a_frag[mt], b_frag[bp][2], b_frag[bp][3]);
                }
        }

        // ---- screening epilogue: s = 2P - C, candidate insert ----
        const int k0 = i * NT;
        #pragma unroll
        for (int mt = 0; mt < 2; mt++)
            #pragma unroll
            for (int h = 0; h < 2; h++) {
                int rl = wm * 32 + mt * 16 + h * 8 + g;
                float thr = ord2f(sh_rmax[rl]) - MARGIN;
                float lmax = -CUDART_INF_F;
                #pragma unroll
                for (int nt = 0; nt < 8; nt++)
                    #pragma unroll
                    for (int q = 0; q < 2; q++) {
                        int col = wn * 64 + nt * 8 + tg * 2 + q;
                        float s = __fmaf_rn(2.0f, acc[mt][nt][h * 2 + q],
                                            -C_s[cur * 128 + col]);
                        if (s > lmax) lmax = s;
                        if (s > thr) {
                            int slot = atomicAdd(&sh_cnt[rl], 1);
                            if (slot < CAP) {
                                g_candk[(size_t)(n0 + rl) * CAP + slot] = (unsigned)(k0 + col);
                                g_cands[(size_t)(n0 + rl) * CAP + slot] = s;
                            }
                        }
                    }
                atomicMax(&sh_rmax[rl], f2ord(lmax));
            }
        __syncthreads();
    }

    if (tid < 128) {
        g_cnt[n0 + tid] = sh_cnt[tid];
        g_thresh[n0 + tid] = ord2f(sh_rmax[tid]) - MARGIN;
    }
}

// ---------------------------------------------------------------------------
// Exact reference-emulated distance (validated bit-exact in R2)
// ---------------------------------------------------------------------------
__device__ __forceinline__ float exact_d(const float* __restrict__ zp,
                                         const float* __restrict__ e,
                                         float A, float C) {
    float P = 0.f;
    #pragma unroll 16
    for (int c = 0; c < CDIM; c++)
        P = __fmaf_rn(__ldg(zp + (size_t)c * 1024), __ldg(e + c), P);
    float t = __fsub_rn(A, __fmul_rn(2.0f, P));
    return __fadd_rn(t, C);
}

// One warp per row: exact argmin (first-index tie-break) over candidate set.
__global__ __launch_bounds__(256)
void rescore_kernel(const float* __restrict__ z, const float* __restrict__ emb) {
    const int wid = threadIdx.x >> 5, lane = threadIdx.x & 31;
    const int n = blockIdx.x * 8 + wid;
    const int b = n >> 10, hw = n & 1023;
    const float* zp = z + (size_t)b * CDIM * 1024 + hw;
    const float A = g_A[n];
    const int cnt = g_cnt[n];
    const float thresh = g_thresh[n];

    float bd = CUDART_INF_F;
    int bi = 0x7fffffff;

    if (cnt <= CAP) {
        for (int base = 0; base < cnt; base += 32) {
            int l = base + lane;
            if (l < cnt) {
                float s = g_cands[(size_t)n * CAP + l];
                if (s >= thresh) {
                    int k = (int)g_candk[(size_t)n * CAP + l];
                    float d = exact_d(zp, emb + (size_t)k * CDIM, A, g_C[k]);
                    if (d < bd || (d == bd && k < bi)) { bd = d; bi = k; }
                }
            }
        }
    } else {  // overflow fallback: exact scan of all codes
        for (int k = lane; k < KCODES; k += 32) {
            float d = exact_d(zp, emb + (size_t)k * CDIM, A, g_C[k]);
            if (d < bd || (d == bd && k < bi)) { bd = d; bi = k; }
        }
    }
    #pragma unroll
    for (int off = 16; off; off >>= 1) {
        float od = __shfl_down_sync(0xffffffffu, bd, off);
        int   oi = __shfl_down_sync(0xffffffffu, bi, off);
        if (od < bd || (od == bd && oi < bi)) { bd = od; bi = oi; }
    }
    if (lane == 0) g_idx[n] = bi;
}

// ---------------------------------------------------------------------------
// Quantize / losses / indices (validated in R2)
// ---------------------------------------------------------------------------
__global__ __launch_bounds__(256)
void quantize_kernel(const float* __restrict__ z, const float* __restrict__ emb,
                     float* __restrict__ out) {
    __shared__ int bidx_s[64];
    __shared__ float red[256];
    const int tid = threadIdx.x;
    const int n0 = blockIdx.x * 64;
    const int bimg = n0 >> 10, hw0 = n0 & 1023;
    const float* zb = z + (size_t)bimg * CDIM * 1024 + hw0;
    const size_t QELEMS = (size_t)NROWS * CDIM;

    if (tid < 64) {
        int k = g_idx[n0 + tid];
        bidx_s[tid] = k;
        out[QELEMS + 2 + n0 + tid] = (float)k;
    }
    __syncthreads();

    float lsum = 0.f;
    for (int e = tid; e < 64 * CDIM; e += 256) {
        int c = e >> 6, m = e & 63;
        float q  = emb[(size_t)bidx_s[m] * CDIM + c];
        float zv = zb[(size_t)c * 1024 + m];
        float d  = __fsub_rn(q, zv);
        out[(size_t)bimg * CDIM * 1024 + (size_t)c * 1024 + hw0 + m] = __fadd_rn(zv, d);
        lsum = __fmaf_rn(d, d, lsum);
    }
    red[tid] = lsum;
    __syncthreads();
    #pragma unroll
    for (int st = 128; st; st >>= 1) {
        if (tid < st) red[tid] += red[tid + st];
        __syncthreads();
    }
    if (tid == 0) g_partial[blockIdx.x] = red[0];
}

__global__ void finalize_kernel(float* __restrict__ out) {
    __shared__ float red[256];
    red[threadIdx.x] = g_partial[threadIdx.x];
    __syncthreads();
    #pragma unroll
    for (int st = 128; st; st >>= 1) {
        if (threadIdx.x < st) red[threadIdx.x] += red[threadIdx.x + st];
        __syncthreads();
    }
    if (threadIdx.x == 0) {
        const size_t QELEMS = (size_t)NROWS * CDIM;
        float loss = red[0] / (float)QELEMS;
        out[QELEMS]     = loss;
        out[QELEMS + 1] = 0.25f * loss;
    }
}

// ---------------------------------------------------------------------------
extern "C" void kernel_launch(void* const* d_in, const int* in_sizes, int n_in,
                              void* d_out, int out_size) {
    const float* z   = (const float*)d_in[0];
    const float* emb = (const float*)d_in[1];
    float* out = (float*)d_out;

    cudaFuncSetAttribute(gemm_screen_kernel,
                         cudaFuncAttributeMaxDynamicSharedMemorySize, SM_TOTAL);

    conv_a_kernel<<<dim3(32, 8, 16), 256>>>(z);
    conv_b_kernel<<<KCODES * CDIM / 4 / 256, 256>>>(emb);
    c_kernel<<<KCODES / 256, 256>>>(emb);
    a_kernel<<<NROWS / 256, 256>>>(z);
    gemm_screen_kernel<<<NROWS / MT, 256, SM_TOTAL>>>();
    rescore_kernel<<<NROWS / 8, 256>>>(z, emb);
    quantize_kernel<<<NROWS / 64, 256>>>(z, emb, out);
    finalize_kernel<<<1, 256>>>(out);
}

// round 5
// speedup vs baseline: 206.7885x; 206.7885x over previous
#include <cuda_runtime.h>
#include <cuda_bf16.h>
#include <cstdint>
#include <math_constants.h>

#define CDIM 256
#define KCODES 8192
#define NROWS 16384
#define NT 128              // codes per chunk
#define MT 128              // rows per CTA
#define NCHUNKS (KCODES / NT)
#define CAP 128             // candidate slots per row
#define MARGIN 1.5e-3f

// ---------------------------------------------------------------------------
// Device globals (allocation-free scratch)
// ---------------------------------------------------------------------------
__device__ __align__(16) __nv_bfloat16 g_Abf[(size_t)NROWS * CDIM];   // [n][c]
__device__ __align__(16) __nv_bfloat16 g_Bbf[(size_t)KCODES * CDIM];  // [k][c]
__device__ float    g_A[NROWS];                          // exact ||x||^2 (strict seq)
__device__ float    g_C[KCODES];                         // exact ||e||^2 (strict seq)
__device__ unsigned g_candk[(size_t)NROWS * CAP];
__device__ float    g_cands[(size_t)NROWS * CAP];
__device__ int      g_cnt[NROWS];
__device__ float    g_thresh[NROWS];
__device__ int      g_idx[NROWS];
__device__ float    g_partial[NROWS / 64];

// ---------------------------------------------------------------------------
// Helpers
// ---------------------------------------------------------------------------
__device__ __forceinline__ uint32_t smem_to_u32(const void* p) {
    uint32_t a;
    asm("{ .reg .u64 t; cvta.to.shared.u64 t, %1; cvt.u32.u64 %0, t; }" : "=r"(a) : "l"(p));
    return a;
}
__device__ __forceinline__ unsigned f2ord(float f) {   // order-preserving float->uint
    unsigned u = __float_as_uint(f);
    return (u & 0x80000000u) ? ~u : (u | 0x80000000u);
}
__device__ __forceinline__ float ord2f(unsigned u) {
    return __uint_as_float((u & 0x80000000u) ? (u ^ 0x80000000u) : ~u);
}
__device__ __forceinline__ void ldsm4(uint32_t r[4], uint32_t addr) {
    asm volatile("ldmatrix.sync.aligned.m8n8.x4.shared.b16 {%0,%1,%2,%3}, [%4];"
                 : "=r"(r[0]), "=r"(r[1]), "=r"(r[2]), "=r"(r[3]) : "r"(addr));
}
__device__ __forceinline__ void mma16816(float d[4], const uint32_t a[4],
                                         uint32_t b0, uint32_t b1) {
    asm("mma.sync.aligned.m16n8k16.row.col.f32.bf16.bf16.f32 "
        "{%0,%1,%2,%3}, {%4,%5,%6,%7}, {%8,%9}, {%0,%1,%2,%3};"
        : "+f"(d[0]), "+f"(d[1]), "+f"(d[2]), "+f"(d[3])
        : "r"(a[0]), "r"(a[1]), "r"(a[2]), "r"(a[3]), "r"(b0), "r"(b1));
}

// ---------------------------------------------------------------------------
// Prep kernels
// ---------------------------------------------------------------------------
__global__ void conv_a_kernel(const float* __restrict__ z) {   // z[b][c][hw] -> Abf[n][c]
    __shared__ float tile[32][33];
    int b = blockIdx.z, hw0 = blockIdx.x * 32, cb = blockIdx.y * 32;
    int tx = threadIdx.x & 31, ty = threadIdx.x >> 5;
    #pragma unroll
    for (int r = ty; r < 32; r += 8)
        tile[r][tx] = z[((size_t)b * CDIM + cb + r) * 1024 + hw0 + tx];
    __syncthreads();
    #pragma unroll
    for (int r = ty; r < 32; r += 8)
        g_Abf[((size_t)b * 1024 + hw0 + r) * CDIM + cb + tx] = __float2bfloat16_rn(tile[tx][r]);
}

__global__ void conv_b_kernel(const float* __restrict__ emb) {
    int i = blockIdx.x * blockDim.x + threadIdx.x;   // over KCODES*CDIM/4
    float4 v = ((const float4*)emb)[i];
    __nv_bfloat162* dst = (__nv_bfloat162*)g_Bbf;
    dst[i * 2]     = __floats2bfloat162_rn(v.x, v.y);
    dst[i * 2 + 1] = __floats2bfloat162_rn(v.z, v.w);
}

__global__ void c_kernel(const float* __restrict__ emb) {   // strict sequential fp32
    int k = blockIdx.x * blockDim.x + threadIdx.x;
    const float* e = emb + (size_t)k * CDIM;
    float s = 0.f;
    for (int c = 0; c < CDIM; c++) {
        float v = __ldg(e + c);
        s = __fadd_rn(s, __fmul_rn(v, v));
    }
    g_C[k] = s;
}

__global__ void a_kernel(const float* __restrict__ z) {     // strict sequential fp32
    int n = blockIdx.x * blockDim.x + threadIdx.x;
    int b = n >> 10, hw = n & 1023;
    const float* zp = z + (size_t)b * CDIM * 1024 + hw;
    float s = 0.f;
    for (int c = 0; c < CDIM; c++) {
        float v = __ldg(zp + (size_t)c * 1024);
        s = __fadd_rn(s, __fmul_rn(v, v));
    }
    g_A[n] = s;
}

// ---------------------------------------------------------------------------
// GEMM (HMMA mma.sync bf16) + two-pass screening
// SMEM layout (bytes): As 0..64K, B0 64K..128K, B1 128K..192K,
//                      C_s 192K (+1KB, 2 x 128 f), runmax (+512), cnt (+512)
// ---------------------------------------------------------------------------
#define SM_A 0
#define SM_B0 65536
#define SM_B1 131072
#define SM_C  196608
#define SM_RMAX (SM_C + 1024)
#define SM_CNT  (SM_RMAX + 512)
#define SM_TOTAL (SM_CNT + 512)

// copy 128 rows x 256 bf16 (64KB) gmem->smem with per-row XOR swizzle
// (16B granule g in row r stored at granule g ^ (r&7); conflict-free LDSM)
__device__ __forceinline__ void st_tile(char* dst, const uint4* __restrict__ src, int tid) {
    #pragma unroll
    for (int it = 0; it < 16; it++) {
        int u = it * 256 + tid;            // 0..4095 uint4
        int row = u >> 5, gr = u & 31;     // 32 granules (512B) per row
        *(uint4*)(dst + row * 512 + ((gr ^ (row & 7)) << 4)) = src[u];
    }
}

__global__ __launch_bounds__(256, 1)
void gemm_screen_kernel() {
    extern __shared__ char smem[];
    const uint32_t smem_base = smem_to_u32(smem);
    const int tid = threadIdx.x;
    const int wid = tid >> 5, lane = tid & 31;
    const int wm = wid >> 1, wn = wid & 1;       // 4x2 warp grid
    const int g = lane >> 2, tg = lane & 3;
    const int n0 = blockIdx.x * MT;

    float*    C_s     = (float*)(smem + SM_C);
    unsigned* sh_rmax = (unsigned*)(smem + SM_RMAX);
    int*      sh_cnt  = (int*)(smem + SM_CNT);

    if (tid < 128) { sh_rmax[tid] = f2ord(-CUDART_INF_F); sh_cnt[tid] = 0; }

    // Prologue: A tile + B chunk 0 + C chunk 0
    st_tile(smem + SM_A, (const uint4*)(g_Abf + (size_t)n0 * CDIM), tid);
    st_tile(smem + SM_B0, (const uint4*)g_Bbf, tid);
    if (tid < 128) C_s[tid] = g_C[tid];
    __syncthreads();

    const uint32_t As_base = smem_base + SM_A;

    for (int i = 0; i < NCHUNKS; i++) {
        const int cur = i & 1, nxt = cur ^ 1;

        // Prefetch next B chunk + C into the other buffer (overlaps with HMMA)
        if (i + 1 < NCHUNKS) {
            st_tile(smem + (nxt ? SM_B1 : SM_B0),
                    (const uint4*)(g_Bbf + (size_t)(i + 1) * NT * CDIM), tid);
            if (tid < 128) C_s[nxt * 128 + tid] = g_C[(i + 1) * NT + tid];
        }

        // ---- compute chunk i ----
        const uint32_t Bs_base = smem_base + (cur ? SM_B1 : SM_B0);
        float acc[2][8][4];
        #pragma unroll
        for (int mt = 0; mt < 2; mt++)
            #pragma unroll
            for (int nt = 0; nt < 8; nt++)
                #pragma unroll
                for (int c = 0; c < 4; c++) acc[mt][nt][c] = 0.f;

        #pragma unroll
        for (int ks = 0; ks < 16; ks++) {
            uint32_t a_frag[2][4];
            #pragma unroll
            for (int mt = 0; mt < 2; mt++) {
                int row = wm * 32 + mt * 16 + (lane & 15);
                int gr  = ks * 2 + (lane >> 4);
                ldsm4(a_frag[mt], As_base + row * 512 + ((gr ^ (row & 7)) << 4));
            }
            uint32_t b_frag[4][4];
            #pragma unroll
            for (int bp = 0; bp < 4; bp++) {
                int n  = wn * 64 + bp * 16 + ((lane >> 4) << 3) + (lane & 7);
                int gr = ks * 2 + ((lane >> 3) & 1);
                ldsm4(b_frag[bp], Bs_base + n * 512 + ((gr ^ (n & 7)) << 4));
            }
            #pragma unroll
            for (int mt = 0; mt < 2; mt++)
                #pragma unroll
                for (int bp = 0; bp < 4; bp++) {
                    mma16816(acc[mt][bp * 2],     a_frag[mt], b_frag[bp][0], b_frag[bp][1]);
                    mma16816(acc[mt][bp * 2 + 1], a_frag[mt], b_frag[bp][2], b_frag[bp][3]);
                }
        }

        // ---- PASS 1: scores in-place + chunk row-max -> sh_rmax ----
        #pragma unroll
        for (int mt = 0; mt < 2; mt++) {
            float lmax[2] = {-CUDART_INF_F, -CUDART_INF_F};
            #pragma unroll
            for (int nt = 0; nt < 8; nt++)
                #pragma unroll
                for (int h = 0; h < 2; h++)
                    #pragma unroll
                    for (int q = 0; q < 2; q++) {
                        int col = wn * 64 + nt * 8 + tg * 2 + q;
                        float s = __fmaf_rn(2.0f, acc[mt][nt][h * 2 + q],
                                            -C_s[cur * 128 + col]);
                        acc[mt][nt][h * 2 + q] = s;       // overwrite with score
                        if (s > lmax[h]) lmax[h] = s;
                    }
            // reduce over the 4 lanes (tg) sharing each row
            #pragma unroll
            for (int h = 0; h < 2; h++) {
                lmax[h] = fmaxf(lmax[h], __shfl_xor_sync(0xffffffffu, lmax[h], 1));
                lmax[h] = fmaxf(lmax[h], __shfl_xor_sync(0xffffffffu, lmax[h], 2));
                if (tg == 0) {
                    int rl = wm * 32 + mt * 16 + h * 8 + g;
                    atomicMax(&sh_rmax[rl], f2ord(lmax[h]));
                }
            }
        }
        __syncthreads();   // runmax now includes this chunk (both wn halves)

        // ---- PASS 2: insert candidates above updated threshold ----
        const int k0 = i * NT;
        #pragma unroll
        for (int mt = 0; mt < 2; mt++)
            #pragma unroll
            for (int h = 0; h < 2; h++) {
                int rl = wm * 32 + mt * 16 + h * 8 + g;
                float thr = ord2f(sh_rmax[rl]) - MARGIN;
                #pragma unroll
                for (int nt = 0; nt < 8; nt++)
                    #pragma unroll
                    for (int q = 0; q < 2; q++) {
                        float s = acc[mt][nt][h * 2 + q];
                        if (s > thr) {
                            int col = wn * 64 + nt * 8 + tg * 2 + q;
                            int slot = atomicAdd(&sh_cnt[rl], 1);
                            if (slot < CAP) {
                                g_candk[(size_t)(n0 + rl) * CAP + slot] = (unsigned)(k0 + col);
                                g_cands[(size_t)(n0 + rl) * CAP + slot] = s;
                            }
                        }
                    }
            }
        __syncthreads();
    }

    if (tid < 128) {
        g_cnt[n0 + tid] = sh_cnt[tid];
        g_thresh[n0 + tid] = ord2f(sh_rmax[tid]) - MARGIN;
    }
}

// ---------------------------------------------------------------------------
// Exact reference-emulated distance (validated bit-exact in R2)
// ---------------------------------------------------------------------------
__device__ __forceinline__ float exact_d(const float* __restrict__ zp,
                                         const float* __restrict__ e,
                                         float A, float C) {
    float P = 0.f;
    #pragma unroll 16
    for (int c = 0; c < CDIM; c++)
        P = __fmaf_rn(__ldg(zp + (size_t)c * 1024), __ldg(e + c), P);
    float t = __fsub_rn(A, __fmul_rn(2.0f, P));
    return __fadd_rn(t, C);
}

// One warp per row: exact argmin (first-index tie-break) over candidate set.
__global__ __launch_bounds__(256)
void rescore_kernel(const float* __restrict__ z, const float* __restrict__ emb) {
    const int wid = threadIdx.x >> 5, lane = threadIdx.x & 31;
    const int n = blockIdx.x * 8 + wid;
    const int b = n >> 10, hw = n & 1023;
    const float* zp = z + (size_t)b * CDIM * 1024 + hw;
    const float A = g_A[n];
    const int cnt = g_cnt[n];
    const float thresh = g_thresh[n];

    float bd = CUDART_INF_F;
    int bi = 0x7fffffff;

    if (cnt <= CAP) {
        for (int base = 0; base < cnt; base += 32) {
            int l = base + lane;
            if (l < cnt) {
                float s = g_cands[(size_t)n * CAP + l];
                if (s >= thresh) {
                    int k = (int)g_candk[(size_t)n * CAP + l];
                    float d = exact_d(zp, emb + (size_t)k * CDIM, A, g_C[k]);
                    if (d < bd || (d == bd && k < bi)) { bd = d; bi = k; }
                }
            }
        }
    } else {  // overflow fallback: exact scan of all codes (safety net)
        for (int k = lane; k < KCODES; k += 32) {
            float d = exact_d(zp, emb + (size_t)k * CDIM, A, g_C[k]);
            if (d < bd || (d == bd && k < bi)) { bd = d; bi = k; }
        }
    }
    #pragma unroll
    for (int off = 16; off; off >>= 1) {
        float od = __shfl_down_sync(0xffffffffu, bd, off);
        int   oi = __shfl_down_sync(0xffffffffu, bi, off);
        if (od < bd || (od == bd && oi < bi)) { bd = od; bi = oi; }
    }
    if (lane == 0) g_idx[n] = bi;
}

// ---------------------------------------------------------------------------
// Quantize / losses / indices (validated in R2)
// ---------------------------------------------------------------------------
__global__ __launch_bounds__(256)
void quantize_kernel(const float* __restrict__ z, const float* __restrict__ emb,
                     float* __restrict__ out) {
    __shared__ int bidx_s[64];
    __shared__ float red[256];
    const int tid = threadIdx.x;
    const int n0 = blockIdx.x * 64;
    const int bimg = n0 >> 10, hw0 = n0 & 1023;
    const float* zb = z + (size_t)bimg * CDIM * 1024 + hw0;
    const size_t QELEMS = (size_t)NROWS * CDIM;

    if (tid < 64) {
        int k = g_idx[n0 + tid];
        bidx_s[tid] = k;
        out[QELEMS + 2 + n0 + tid] = (float)k;
    }
    __syncthreads();

    float lsum = 0.f;
    for (int e = tid; e < 64 * CDIM; e += 256) {
        int c = e >> 6, m = e & 63;
        float q  = emb[(size_t)bidx_s[m] * CDIM + c];
        float zv = zb[(size_t)c * 1024 + m];
        float d  = __fsub_rn(q, zv);
        out[(size_t)bimg * CDIM * 1024 + (size_t)c * 1024 + hw0 + m] = __fadd_rn(zv, d);
        lsum = __fmaf_rn(d, d, lsum);
    }
    red[tid] = lsum;
    __syncthreads();
    #pragma unroll
    for (int st = 128; st; st >>= 1) {
        if (tid < st) red[tid] += red[tid + st];
        __syncthreads();
    }
    if (tid == 0) g_partial[blockIdx.x] = red[0];
}

__global__ void finalize_kernel(float* __restrict__ out) {
    __shared__ float red[256];
    red[threadIdx.x] = g_partial[threadIdx.x];
    __syncthreads();
    #pragma unroll
    for (int st = 128; st; st >>= 1) {
        if (threadIdx.x < st) red[threadIdx.x] += red[threadIdx.x + st];
        __syncthreads();
    }
    if (threadIdx.x == 0) {
        const size_t QELEMS = (size_t)NROWS * CDIM;
        float loss = red[0] / (float)QELEMS;
        out[QELEMS]     = loss;
        out[QELEMS + 1] = 0.25f * loss;
    }
}

// ---------------------------------------------------------------------------
extern "C" void kernel_launch(void* const* d_in, const int* in_sizes, int n_in,
                              void* d_out, int out_size) {
    const float* z   = (const float*)d_in[0];
    const float* emb = (const float*)d_in[1];
    float* out = (float*)d_out;

    cudaFuncSetAttribute(gemm_screen_kernel,
                         cudaFuncAttributeMaxDynamicSharedMemorySize, SM_TOTAL);

    conv_a_kernel<<<dim3(32, 8, 16), 256>>>(z);
    conv_b_kernel<<<KCODES * CDIM / 4 / 256, 256>>>(emb);
    c_kernel<<<KCODES / 256, 256>>>(emb);
    a_kernel<<<NROWS / 256, 256>>>(z);
    gemm_screen_kernel<<<NROWS / MT, 256, SM_TOTAL>>>();
    rescore_kernel<<<NROWS / 8, 256>>>(z, emb);
    quantize_kernel<<<NROWS / 64, 256>>>(z, emb, out);
    finalize_kernel<<<1, 256>>>(out);
}

// round 6
// speedup vs baseline: 282.6265x; 1.3667x over previous
#include <cuda_runtime.h>
#include <cuda_bf16.h>
#include <cstdint>
#include <math_constants.h>

#define CDIM 256
#define KCODES 8192
#define NROWS 16384
#define NT 128              // codes per chunk
#define MT 128              // rows per CTA
#define NCHUNKS (KCODES / NT)
#define CAP 128             // candidate slots per row
#define MARGIN 1.0e-3f

// ---------------------------------------------------------------------------
// Device globals (allocation-free scratch)
// ---------------------------------------------------------------------------
__device__ __align__(16) __nv_bfloat16 g_Abf[(size_t)NROWS * CDIM];   // [n][c]
__device__ __align__(16) __nv_bfloat16 g_Bbf[(size_t)KCODES * CDIM];  // [k][c]
__device__ float    g_A[NROWS];                          // exact ||x||^2 (strict seq)
__device__ float    g_C[KCODES];                         // exact ||e||^2 (strict seq)
__device__ unsigned g_candk[(size_t)NROWS * CAP];
__device__ float    g_cands[(size_t)NROWS * CAP];
__device__ int      g_cnt[NROWS];
__device__ float    g_thresh[NROWS];
__device__ int      g_idx[NROWS];
__device__ float    g_partial[NROWS / 64];

// ---------------------------------------------------------------------------
// Helpers
// ---------------------------------------------------------------------------
__device__ __forceinline__ uint32_t smem_to_u32(const void* p) {
    uint32_t a;
    asm("{ .reg .u64 t; cvta.to.shared.u64 t, %1; cvt.u32.u64 %0, t; }" : "=r"(a) : "l"(p));
    return a;
}
__device__ __forceinline__ unsigned f2ord(float f) {   // order-preserving float->uint
    unsigned u = __float_as_uint(f);
    return (u & 0x80000000u) ? ~u : (u | 0x80000000u);
}
__device__ __forceinline__ float ord2f(unsigned u) {
    return __uint_as_float((u & 0x80000000u) ? (u ^ 0x80000000u) : ~u);
}
__device__ __forceinline__ void ldsm4(uint32_t r[4], uint32_t addr) {
    asm volatile("ldmatrix.sync.aligned.m8n8.x4.shared.b16 {%0,%1,%2,%3}, [%4];"
                 : "=r"(r[0]), "=r"(r[1]), "=r"(r[2]), "=r"(r[3]) : "r"(addr));
}
__device__ __forceinline__ void mma16816(float d[4], const uint32_t a[4],
                                         uint32_t b0, uint32_t b1) {
    asm("mma.sync.aligned.m16n8k16.row.col.f32.bf16.bf16.f32 "
        "{%0,%1,%2,%3}, {%4,%5,%6,%7}, {%8,%9}, {%0,%1,%2,%3};"
        : "+f"(d[0]), "+f"(d[1]), "+f"(d[2]), "+f"(d[3])
        : "r"(a[0]), "r"(a[1]), "r"(a[2]), "r"(a[3]), "r"(b0), "r"(b1));
}
__device__ __forceinline__ void cp16(uint32_t dst, const void* src) {
    asm volatile("cp.async.cg.shared.global [%0], [%1], 16;" :: "r"(dst), "l"(src) : "memory");
}
#define CP_COMMIT() asm volatile("cp.async.commit_group;" ::: "memory")
#define CP_WAIT0()  asm volatile("cp.async.wait_group 0;" ::: "memory")

// ---------------------------------------------------------------------------
// Prep kernels
// ---------------------------------------------------------------------------
__global__ void conv_a_kernel(const float* __restrict__ z) {   // z[b][c][hw] -> Abf[n][c]
    __shared__ float tile[32][33];
    int b = blockIdx.z, hw0 = blockIdx.x * 32, cb = blockIdx.y * 32;
    int tx = threadIdx.x & 31, ty = threadIdx.x >> 5;
    #pragma unroll
    for (int r = ty; r < 32; r += 8)
        tile[r][tx] = z[((size_t)b * CDIM + cb + r) * 1024 + hw0 + tx];
    __syncthreads();
    #pragma unroll
    for (int r = ty; r < 32; r += 8)
        g_Abf[((size_t)b * 1024 + hw0 + r) * CDIM + cb + tx] = __float2bfloat16_rn(tile[tx][r]);
}

__global__ void conv_b_kernel(const float* __restrict__ emb) {
    int i = blockIdx.x * blockDim.x + threadIdx.x;   // over KCODES*CDIM/4
    float4 v = ((const float4*)emb)[i];
    __nv_bfloat162* dst = (__nv_bfloat162*)g_Bbf;
    dst[i * 2]     = __floats2bfloat162_rn(v.x, v.y);
    dst[i * 2 + 1] = __floats2bfloat162_rn(v.z, v.w);
}

// C_k = strict-sequential sum of e^2 (bit-exact), smem-staged for coalescing.
__global__ __launch_bounds__(128)
void c_kernel(const float* __restrict__ emb) {
    __shared__ float tile[128][33];
    const int k0 = blockIdx.x * 128;
    const int tid = threadIdx.x;
    float s = 0.f;
    for (int cb = 0; cb < 8; cb++) {
        __syncthreads();
        for (int u = tid; u < 128 * 32; u += 128) {
            int r = u >> 5, cc = u & 31;   // warp = one 128B row: coalesced
            tile[r][cc] = emb[(size_t)(k0 + r) * CDIM + cb * 32 + cc];
        }
        __syncthreads();
        #pragma unroll
        for (int cc = 0; cc < 32; cc++) {
            float v = tile[tid][cc];
            s = __fadd_rn(s, __fmul_rn(v, v));
        }
    }
    g_C[k0 + tid] = s;
}

__global__ __launch_bounds__(128)
void a_kernel(const float* __restrict__ z) {     // strict sequential fp32
    int n = blockIdx.x * blockDim.x + threadIdx.x;
    int b = n >> 10, hw = n & 1023;
    const float* zp = z + (size_t)b * CDIM * 1024 + hw;
    float s = 0.f;
    for (int c = 0; c < CDIM; c++) {
        float v = __ldg(zp + (size_t)c * 1024);   // lanes: consecutive hw, coalesced
        s = __fadd_rn(s, __fmul_rn(v, v));
    }
    g_A[n] = s;
}

// ---------------------------------------------------------------------------
// GEMM (HMMA mma.sync bf16) + two-pass screening, cp.async prefetch
// SMEM layout (bytes): As 0..64K, B0 64K..128K, B1 128K..192K,
//                      C_s 192K (+1KB, 2 x 128 f), runmax (+512), cnt (+512)
// ---------------------------------------------------------------------------
#define SM_A 0
#define SM_B0 65536
#define SM_B1 131072
#define SM_C  196608
#define SM_RMAX (SM_C + 1024)
#define SM_CNT  (SM_RMAX + 512)
#define SM_TOTAL (SM_CNT + 512)

// async-copy 128 rows x 256 bf16 (64KB) gmem->smem, per-row XOR swizzle
// (16B granule g of row r stored at granule g ^ (r&7): conflict-free LDSM)
__device__ __forceinline__ void cp_tile(uint32_t dst, const __nv_bfloat16* gsrc, int tid) {
    const char* src = (const char*)gsrc;
    #pragma unroll
    for (int it = 0; it < 16; it++) {
        int u = it * 256 + tid;            // 0..4095 granules of 16B
        int row = u >> 5, gr = u & 31;     // 32 granules (512B) per row
        cp16(dst + row * 512 + ((gr ^ (row & 7)) << 4), src + (size_t)u * 16);
    }
}

__global__ __launch_bounds__(256, 1)
void gemm_screen_kernel() {
    extern __shared__ char smem[];
    const uint32_t smem_base = smem_to_u32(smem);
    const int tid = threadIdx.x;
    const int wid = tid >> 5, lane = tid & 31;
    const int wm = wid >> 1, wn = wid & 1;       // 4x2 warp grid
    const int g = lane >> 2, tg = lane & 3;
    const int n0 = blockIdx.x * MT;

    float*    C_s     = (float*)(smem + SM_C);
    unsigned* sh_rmax = (unsigned*)(smem + SM_RMAX);
    int*      sh_cnt  = (int*)(smem + SM_CNT);

    if (tid < 128) { sh_rmax[tid] = f2ord(-CUDART_INF_F); sh_cnt[tid] = 0; }

    // Prologue: async A tile + B chunk 0; C chunk 0 regular
    cp_tile(smem_base + SM_A, g_Abf + (size_t)n0 * CDIM, tid);
    cp_tile(smem_base + SM_B0, g_Bbf, tid);
    CP_COMMIT();
    if (tid < 128) C_s[tid] = g_C[tid];
    CP_WAIT0();
    __syncthreads();

    const uint32_t As_base = smem_base + SM_A;

    for (int i = 0; i < NCHUNKS; i++) {
        const int cur = i & 1, nxt = cur ^ 1;

        // Async prefetch next B chunk (+C) — overlaps the whole MMA body
        if (i + 1 < NCHUNKS) {
            cp_tile(smem_base + (nxt ? SM_B1 : SM_B0),
                    g_Bbf + (size_t)(i + 1) * NT * CDIM, tid);
            CP_COMMIT();
            if (tid < 128) C_s[nxt * 128 + tid] = g_C[(i + 1) * NT + tid];
        }

        // ---- compute chunk i ----
        const uint32_t Bs_base = smem_base + (cur ? SM_B1 : SM_B0);
        float acc[2][8][4];
        #pragma unroll
        for (int mt = 0; mt < 2; mt++)
            #pragma unroll
            for (int nt = 0; nt < 8; nt++)
                #pragma unroll
                for (int c = 0; c < 4; c++) acc[mt][nt][c] = 0.f;

        #pragma unroll
        for (int ks = 0; ks < 16; ks++) {
            uint32_t a_frag[2][4];
            #pragma unroll
            for (int mt = 0; mt < 2; mt++) {
                int row = wm * 32 + mt * 16 + (lane & 15);
                int gr  = ks * 2 + (lane >> 4);
                ldsm4(a_frag[mt], As_base + row * 512 + ((gr ^ (row & 7)) << 4));
            }
            uint32_t b_frag[4][4];
            #pragma unroll
            for (int bp = 0; bp < 4; bp++) {
                int n  = wn * 64 + bp * 16 + ((lane >> 4) << 3) + (lane & 7);
                int gr = ks * 2 + ((lane >> 3) & 1);
                ldsm4(b_frag[bp], Bs_base + n * 512 + ((gr ^ (n & 7)) << 4));
            }
            #pragma unroll
            for (int mt = 0; mt < 2; mt++)
                #pragma unroll
                for (int bp = 0; bp < 4; bp++) {
                    mma16816(acc[mt][bp * 2],     a_frag[mt], b_frag[bp][0], b_frag[bp][1]);
                    mma16816(acc[mt][bp * 2 + 1], a_frag[mt], b_frag[bp][2], b_frag[bp][3]);
                }
        }

        // ---- PASS 1: scores in-place + chunk row-max -> sh_rmax ----
        #pragma unroll
        for (int mt = 0; mt < 2; mt++) {
            float lmax[2] = {-CUDART_INF_F, -CUDART_INF_F};
            #pragma unroll
            for (int nt = 0; nt < 8; nt++)
                #pragma unroll
                for (int h = 0; h < 2; h++)
                    #pragma unroll
                    for (int q = 0; q < 2; q++) {
                        int col = wn * 64 + nt * 8 + tg * 2 + q;
                        float s = __fmaf_rn(2.0f, acc[mt][nt][h * 2 + q],
                                            -C_s[cur * 128 + col]);
                        acc[mt][nt][h * 2 + q] = s;       // overwrite with score
                        if (s > lmax[h]) lmax[h] = s;
                    }
            #pragma unroll
            for (int h = 0; h < 2; h++) {
                lmax[h] = fmaxf(lmax[h], __shfl_xor_sync(0xffffffffu, lmax[h], 1));
                lmax[h] = fmaxf(lmax[h], __shfl_xor_sync(0xffffffffu, lmax[h], 2));
                if (tg == 0) {
                    int rl = wm * 32 + mt * 16 + h * 8 + g;
                    atomicMax(&sh_rmax[rl], f2ord(lmax[h]));
                }
            }
        }
        __syncthreads();   // runmax now includes this chunk (both wn halves)

        // ---- PASS 2: insert candidates above updated threshold ----
        const int k0 = i * NT;
        #pragma unroll
        for (int mt = 0; mt < 2; mt++)
            #pragma unroll
            for (int h = 0; h < 2; h++) {
                int rl = wm * 32 + mt * 16 + h * 8 + g;
                float thr = ord2f(sh_rmax[rl]) - MARGIN;
                #pragma unroll
                for (int nt = 0; nt < 8; nt++)
                    #pragma unroll
                    for (int q = 0; q < 2; q++) {
                        float s = acc[mt][nt][h * 2 + q];
                        if (s > thr) {
                            int col = wn * 64 + nt * 8 + tg * 2 + q;
                            int slot = atomicAdd(&sh_cnt[rl], 1);
                            if (slot < CAP) {
                                g_candk[(size_t)(n0 + rl) * CAP + slot] = (unsigned)(k0 + col);
                                g_cands[(size_t)(n0 + rl) * CAP + slot] = s;
                            }
                        }
                    }
            }
        if (i + 1 < NCHUNKS) CP_WAIT0();   // B(i+1) landed during the MMA body
        __syncthreads();
    }

    if (tid < 128) {
        g_cnt[n0 + tid] = sh_cnt[tid];
        g_thresh[n0 + tid] = ord2f(sh_rmax[tid]) - MARGIN;
    }
}

// ---------------------------------------------------------------------------
// Exact reference-emulated distance (validated bit-exact in R2)
// ---------------------------------------------------------------------------
__device__ __forceinline__ float exact_d(const float* __restrict__ zp,
                                         const float* __restrict__ e,
                                         float A, float C) {
    float P = 0.f;
    #pragma unroll 16
    for (int c = 0; c < CDIM; c++)
        P = __fmaf_rn(__ldg(zp + (size_t)c * 1024), __ldg(e + c), P);
    float t = __fsub_rn(A, __fmul_rn(2.0f, P));
    return __fadd_rn(t, C);
}

// One warp per row: exact argmin (first-index tie-break) over candidate set.
__global__ __launch_bounds__(256)
void rescore_kernel(const float* __restrict__ z, const float* __restrict__ emb) {
    const int wid = threadIdx.x >> 5, lane = threadIdx.x & 31;
    const int n = blockIdx.x * 8 + wid;
    const int b = n >> 10, hw = n & 1023;
    const float* zp = z + (size_t)b * CDIM * 1024 + hw;
    const float A = g_A[n];
    const int cnt = g_cnt[n];
    const float thresh = g_thresh[n];

    float bd = CUDART_INF_F;
    int bi = 0x7fffffff;

    if (cnt <= CAP) {
        for (int base = 0; base < cnt; base += 32) {
            int l = base + lane;
            if (l < cnt) {
                float s = g_cands[(size_t)n * CAP + l];
                if (s >= thresh) {
                    int k = (int)g_candk[(size_t)n * CAP + l];
                    float d = exact_d(zp, emb + (size_t)k * CDIM, A, g_C[k]);
                    if (d < bd || (d == bd && k < bi)) { bd = d; bi = k; }
                }
            }
        }
    } else {  // overflow fallback: exact scan of all codes (safety net)
        for (int k = lane; k < KCODES; k += 32) {
            float d = exact_d(zp, emb + (size_t)k * CDIM, A, g_C[k]);
            if (d < bd || (d == bd && k < bi)) { bd = d; bi = k; }
        }
    }
    #pragma unroll
    for (int off = 16; off; off >>= 1) {
        float od = __shfl_down_sync(0xffffffffu, bd, off);
        int   oi = __shfl_down_sync(0xffffffffu, bi, off);
        if (od < bd || (od == bd && oi < bi)) { bd = od; bi = oi; }
    }
    if (lane == 0) g_idx[n] = bi;
}

// ---------------------------------------------------------------------------
// Quantize / losses / indices (validated in R2)
// ---------------------------------------------------------------------------
__global__ __launch_bounds__(256)
void quantize_kernel(const float* __restrict__ z, const float* __restrict__ emb,
                     float* __restrict__ out) {
    __shared__ int bidx_s[64];
    __shared__ float red[256];
    const int tid = threadIdx.x;
    const int n0 = blockIdx.x * 64;
    const int bimg = n0 >> 10, hw0 = n0 & 1023;
    const float* zb = z + (size_t)bimg * CDIM * 1024 + hw0;
    const size_t QELEMS = (size_t)NROWS * CDIM;

    if (tid < 64) {
        int k = g_idx[n0 + tid];
        bidx_s[tid] = k;
        out[QELEMS + 2 + n0 + tid] = (float)k;
    }
    __syncthreads();

    float lsum = 0.f;
    for (int e = tid; e < 64 * CDIM; e += 256) {
        int c = e >> 6, m = e & 63;
        float q  = emb[(size_t)bidx_s[m] * CDIM + c];
        float zv = zb[(size_t)c * 1024 + m];
        float d  = __fsub_rn(q, zv);
        out[(size_t)bimg * CDIM * 1024 + (size_t)c * 1024 + hw0 + m] = __fadd_rn(zv, d);
        lsum = __fmaf_rn(d, d, lsum);
    }
    red[tid] = lsum;
    __syncthreads();
    #pragma unroll
    for (int st = 128; st; st >>= 1) {
        if (tid < st) red[tid] += red[tid + st];
        __syncthreads();
    }
    if (tid == 0) g_partial[blockIdx.x] = red[0];
}

__global__ void finalize_kernel(float* __restrict__ out) {
    __shared__ float red[256];
    red[threadIdx.x] = g_partial[threadIdx.x];
    __syncthreads();
    #pragma unroll
    for (int st = 128; st; st >>= 1) {
        if (threadIdx.x < st) red[threadIdx.x] += red[threadIdx.x + st];
        __syncthreads();
    }
    if (threadIdx.x == 0) {
        const size_t QELEMS = (size_t)NROWS * CDIM;
        float loss = red[0] / (float)QELEMS;
        out[QELEMS]     = loss;
        out[QELEMS + 1] = 0.25f * loss;
    }
}

// ---------------------------------------------------------------------------
extern "C" void kernel_launch(void* const* d_in, const int* in_sizes, int n_in,
                              void* d_out, int out_size) {
    const float* z   = (const float*)d_in[0];
    const float* emb = (const float*)d_in[1];
    float* out = (float*)d_out;

    cudaFuncSetAttribute(gemm_screen_kernel,
                         cudaFuncAttributeMaxDynamicSharedMemorySize, SM_TOTAL);

    conv_a_kernel<<<dim3(32, 8, 16), 256>>>(z);
    conv_b_kernel<<<KCODES * CDIM / 4 / 256, 256>>>(emb);
    c_kernel<<<KCODES / 128, 128>>>(emb);
    a_kernel<<<NROWS / 128, 128>>>(z);
    gemm_screen_kernel<<<NROWS / MT, 256, SM_TOTAL>>>();
    rescore_kernel<<<NROWS / 8, 256>>>(z, emb);
    quantize_kernel<<<NROWS / 64, 256>>>(z, emb, out);
    finalize_kernel<<<1, 256>>>(out);
}

// round 7
// speedup vs baseline: 303.6746x; 1.0745x over previous
#include <cuda_runtime.h>
#include <cuda_bf16.h>
#include <cstdint>
#include <math_constants.h>

#define CDIM 256
#define KCODES 8192
#define NROWS 16384
#define NT 128              // codes per chunk
#define MT 128              // rows per CTA
#define NCHUNKS (KCODES / NT)
#define CAP 128             // candidate slots per row
#define MARGIN 1.0e-3f
#define GTHREADS 512

// ---------------------------------------------------------------------------
// Device globals (allocation-free scratch)
// ---------------------------------------------------------------------------
__device__ __align__(16) __nv_bfloat16 g_Abf[(size_t)NROWS * CDIM];   // [n][c]
__device__ __align__(16) __nv_bfloat16 g_Bbf[(size_t)KCODES * CDIM];  // [k][c]
__device__ float    g_A[NROWS];                          // exact ||x||^2 (strict seq)
__device__ float    g_C[KCODES];                         // exact ||e||^2 (strict seq)
__device__ unsigned g_candk[(size_t)NROWS * CAP];
__device__ float    g_cands[(size_t)NROWS * CAP];
__device__ int      g_cnt[NROWS];
__device__ float    g_thresh[NROWS];
__device__ int      g_idx[NROWS];
__device__ float    g_partial[NROWS / 64];

// ---------------------------------------------------------------------------
// Helpers
// ---------------------------------------------------------------------------
__device__ __forceinline__ uint32_t smem_to_u32(const void* p) {
    uint32_t a;
    asm("{ .reg .u64 t; cvta.to.shared.u64 t, %1; cvt.u32.u64 %0, t; }" : "=r"(a) : "l"(p));
    return a;
}
__device__ __forceinline__ unsigned f2ord(float f) {   // order-preserving float->uint
    unsigned u = __float_as_uint(f);
    return (u & 0x80000000u) ? ~u : (u | 0x80000000u);
}
__device__ __forceinline__ float ord2f(unsigned u) {
    return __uint_as_float((u & 0x80000000u) ? (u ^ 0x80000000u) : ~u);
}
__device__ __forceinline__ void ldsm4(uint32_t r[4], uint32_t addr) {
    asm volatile("ldmatrix.sync.aligned.m8n8.x4.shared.b16 {%0,%1,%2,%3}, [%4];"
                 : "=r"(r[0]), "=r"(r[1]), "=r"(r[2]), "=r"(r[3]) : "r"(addr));
}
__device__ __forceinline__ void mma16816(float d[4], const uint32_t a[4],
                                         uint32_t b0, uint32_t b1) {
    asm("mma.sync.aligned.m16n8k16.row.col.f32.bf16.bf16.f32 "
        "{%0,%1,%2,%3}, {%4,%5,%6,%7}, {%8,%9}, {%0,%1,%2,%3};"
        : "+f"(d[0]), "+f"(d[1]), "+f"(d[2]), "+f"(d[3])
        : "r"(a[0]), "r"(a[1]), "r"(a[2]), "r"(a[3]), "r"(b0), "r"(b1));
}
__device__ __forceinline__ void cp16(uint32_t dst, const void* src) {
    asm volatile("cp.async.cg.shared.global [%0], [%1], 16;" :: "r"(dst), "l"(src) : "memory");
}
#define CP_COMMIT() asm volatile("cp.async.commit_group;" ::: "memory")
#define CP_WAIT0()  asm volatile("cp.async.wait_group 0;" ::: "memory")

// ---------------------------------------------------------------------------
// Prep kernels
// ---------------------------------------------------------------------------
__global__ void conv_a_kernel(const float* __restrict__ z) {   // z[b][c][hw] -> Abf[n][c]
    __shared__ float tile[32][33];
    int b = blockIdx.z, hw0 = blockIdx.x * 32, cb = blockIdx.y * 32;
    int tx = threadIdx.x & 31, ty = threadIdx.x >> 5;
    #pragma unroll
    for (int r = ty; r < 32; r += 8)
        tile[r][tx] = z[((size_t)b * CDIM + cb + r) * 1024 + hw0 + tx];
    __syncthreads();
    #pragma unroll
    for (int r = ty; r < 32; r += 8)
        g_Abf[((size_t)b * 1024 + hw0 + r) * CDIM + cb + tx] = __float2bfloat16_rn(tile[tx][r]);
}

__global__ void conv_b_kernel(const float* __restrict__ emb) {
    int i = blockIdx.x * blockDim.x + threadIdx.x;   // over KCODES*CDIM/4
    float4 v = ((const float4*)emb)[i];
    __nv_bfloat162* dst = (__nv_bfloat162*)g_Bbf;
    dst[i * 2]     = __floats2bfloat162_rn(v.x, v.y);
    dst[i * 2 + 1] = __floats2bfloat162_rn(v.z, v.w);
}

// C_k = strict-sequential sum of e^2 (bit-exact), smem-staged for coalescing.
__global__ __launch_bounds__(128)
void c_kernel(const float* __restrict__ emb) {
    __shared__ float tile[128][33];
    const int k0 = blockIdx.x * 128;
    const int tid = threadIdx.x;
    float s = 0.f;
    for (int cb = 0; cb < 8; cb++) {
        __syncthreads();
        for (int u = tid; u < 128 * 32; u += 128) {
            int r = u >> 5, cc = u & 31;   // warp = one 128B row: coalesced
            tile[r][cc] = emb[(size_t)(k0 + r) * CDIM + cb * 32 + cc];
        }
        __syncthreads();
        #pragma unroll
        for (int cc = 0; cc < 32; cc++) {
            float v = tile[tid][cc];
            s = __fadd_rn(s, __fmul_rn(v, v));
        }
    }
    g_C[k0 + tid] = s;
}

// A_n strict-sequential; loads batched 8-wide (MLP), accumulation order unchanged.
__global__ __launch_bounds__(256)
void a_kernel(const float* __restrict__ z) {
    int n = blockIdx.x * blockDim.x + threadIdx.x;
    int b = n >> 10, hw = n & 1023;
    const float* zp = z + (size_t)b * CDIM * 1024 + hw;
    float s = 0.f;
    for (int c0 = 0; c0 < CDIM; c0 += 8) {
        float v[8];
        #pragma unroll
        for (int u = 0; u < 8; u++) v[u] = __ldg(zp + (size_t)(c0 + u) * 1024);
        #pragma unroll
        for (int u = 0; u < 8; u++) s = __fadd_rn(s, __fmul_rn(v[u], v[u]));
    }
    g_A[n] = s;
}

// ---------------------------------------------------------------------------
// GEMM (HMMA mma.sync bf16) + two-pass screening, cp.async prefetch.
// 512 threads, 16 warps in 4(M) x 4(N) grid, warp tile 32x32.
// SMEM layout (bytes): As 0..64K, B0 64K..128K, B1 128K..192K,
//                      C_s 192K (+1KB, 2 x 128 f), runmax (+512), cnt (+512)
// ---------------------------------------------------------------------------
#define SM_A 0
#define SM_B0 65536
#define SM_B1 131072
#define SM_C  196608
#define SM_RMAX (SM_C + 1024)
#define SM_CNT  (SM_RMAX + 512)
#define SM_TOTAL (SM_CNT + 512)

// async-copy 128 rows x 256 bf16 (64KB) gmem->smem, per-row XOR swizzle
// (16B granule g of row r stored at granule g ^ (r&7): conflict-free LDSM)
__device__ __forceinline__ void cp_tile(uint32_t dst, const __nv_bfloat16* gsrc, int tid) {
    const char* src = (const char*)gsrc;
    #pragma unroll
    for (int it = 0; it < 8; it++) {
        int u = it * GTHREADS + tid;       // 0..4095 granules of 16B
        int row = u >> 5, gr = u & 31;     // 32 granules (512B) per row
        cp16(dst + row * 512 + ((gr ^ (row & 7)) << 4), src + (size_t)u * 16);
    }
}

__global__ __launch_bounds__(GTHREADS, 1)
void gemm_screen_kernel() {
    extern __shared__ char smem[];
    const uint32_t smem_base = smem_to_u32(smem);
    const int tid = threadIdx.x;
    const int wid = tid >> 5, lane = tid & 31;
    const int wm = wid & 3, wn = wid >> 2;       // 4x4 warp grid
    const int g = lane >> 2, tg = lane & 3;
    const int n0 = blockIdx.x * MT;

    float*    C_s     = (float*)(smem + SM_C);
    unsigned* sh_rmax = (unsigned*)(smem + SM_RMAX);
    int*      sh_cnt  = (int*)(smem + SM_CNT);

    if (tid < 128) { sh_rmax[tid] = f2ord(-CUDART_INF_F); sh_cnt[tid] = 0; }

    // Prologue: async A tile + B chunk 0; C chunk 0 regular
    cp_tile(smem_base + SM_A, g_Abf + (size_t)n0 * CDIM, tid);
    cp_tile(smem_base + SM_B0, g_Bbf, tid);
    CP_COMMIT();
    if (tid < 128) C_s[tid] = g_C[tid];
    CP_WAIT0();
    __syncthreads();

    const uint32_t As_base = smem_base + SM_A;

    for (int i = 0; i < NCHUNKS; i++) {
        const int cur = i & 1, nxt = cur ^ 1;

        // Async prefetch next B chunk (+C) — overlaps the whole MMA body
        if (i + 1 < NCHUNKS) {
            cp_tile(smem_base + (nxt ? SM_B1 : SM_B0),
                    g_Bbf + (size_t)(i + 1) * NT * CDIM, tid);
            CP_COMMIT();
            if (tid < 128) C_s[nxt * 128 + tid] = g_C[(i + 1) * NT + tid];
        }

        // ---- compute chunk i: warp tile 32(M) x 32(N) ----
        const uint32_t Bs_base = smem_base + (cur ? SM_B1 : SM_B0);
        float acc[2][4][4];
        #pragma unroll
        for (int mt = 0; mt < 2; mt++)
            #pragma unroll
            for (int nt = 0; nt < 4; nt++)
                #pragma unroll
                for (int c = 0; c < 4; c++) acc[mt][nt][c] = 0.f;

        #pragma unroll
        for (int ks = 0; ks < 16; ks++) {
            uint32_t a_frag[2][4];
            #pragma unroll
            for (int mt = 0; mt < 2; mt++) {
                int row = wm * 32 + mt * 16 + (lane & 15);
                int gr  = ks * 2 + (lane >> 4);
                ldsm4(a_frag[mt], As_base + row * 512 + ((gr ^ (row & 7)) << 4));
            }
            uint32_t b_frag[2][4];
            #pragma unroll
            for (int bp = 0; bp < 2; bp++) {
                int n  = wn * 32 + bp * 16 + ((lane >> 4) << 3) + (lane & 7);
                int gr = ks * 2 + ((lane >> 3) & 1);
                ldsm4(b_frag[bp], Bs_base + n * 512 + ((gr ^ (n & 7)) << 4));
            }
            #pragma unroll
            for (int mt = 0; mt < 2; mt++)
                #pragma unroll
                for (int bp = 0; bp < 2; bp++) {
                    mma16816(acc[mt][bp * 2],     a_frag[mt], b_frag[bp][0], b_frag[bp][1]);
                    mma16816(acc[mt][bp * 2 + 1], a_frag[mt], b_frag[bp][2], b_frag[bp][3]);
                }
        }

        // ---- PASS 1: scores in-place + chunk row-max -> sh_rmax ----
        #pragma unroll
        for (int mt = 0; mt < 2; mt++) {
            float lmax[2] = {-CUDART_INF_F, -CUDART_INF_F};
            #pragma unroll
            for (int nt = 0; nt < 4; nt++)
                #pragma unroll
                for (int h = 0; h < 2; h++)
                    #pragma unroll
                    for (int q = 0; q < 2; q++) {
                        int col = wn * 32 + nt * 8 + tg * 2 + q;
                        float s = __fmaf_rn(2.0f, acc[mt][nt][h * 2 + q],
                                            -C_s[cur * 128 + col]);
                        acc[mt][nt][h * 2 + q] = s;       // overwrite with score
                        if (s > lmax[h]) lmax[h] = s;
                    }
            #pragma unroll
            for (int h = 0; h < 2; h++) {
                lmax[h] = fmaxf(lmax[h], __shfl_xor_sync(0xffffffffu, lmax[h], 1));
                lmax[h] = fmaxf(lmax[h], __shfl_xor_sync(0xffffffffu, lmax[h], 2));
                if (tg == 0) {
                    int rl = wm * 32 + mt * 16 + h * 8 + g;
                    atomicMax(&sh_rmax[rl], f2ord(lmax[h]));
                }
            }
        }
        __syncthreads();   // runmax now includes this chunk (all wn quarters)

        // ---- PASS 2: insert candidates above updated threshold ----
        const int k0 = i * NT;
        #pragma unroll
        for (int mt = 0; mt < 2; mt++)
            #pragma unroll
            for (int h = 0; h < 2; h++) {
                int rl = wm * 32 + mt * 16 + h * 8 + g;
                float thr = ord2f(sh_rmax[rl]) - MARGIN;
                #pragma unroll
                for (int nt = 0; nt < 4; nt++)
                    #pragma unroll
                    for (int q = 0; q < 2; q++) {
                        float s = acc[mt][nt][h * 2 + q];
                        if (s > thr) {
                            int col = wn * 32 + nt * 8 + tg * 2 + q;
                            int slot = atomicAdd(&sh_cnt[rl], 1);
                            if (slot < CAP) {
                                g_candk[(size_t)(n0 + rl) * CAP + slot] = (unsigned)(k0 + col);
                                g_cands[(size_t)(n0 + rl) * CAP + slot] = s;
                            }
                        }
                    }
            }
        if (i + 1 < NCHUNKS) CP_WAIT0();   // B(i+1) landed during the MMA body
        __syncthreads();
    }

    if (tid < 128) {
        g_cnt[n0 + tid] = sh_cnt[tid];
        g_thresh[n0 + tid] = ord2f(sh_rmax[tid]) - MARGIN;
    }
}

// ---------------------------------------------------------------------------
// Exact reference-emulated distance (validated bit-exact in R2)
// ---------------------------------------------------------------------------
__device__ __forceinline__ float exact_d(const float* __restrict__ zp,
                                         const float* __restrict__ e,
                                         float A, float C) {
    float P = 0.f;
    #pragma unroll 16
    for (int c = 0; c < CDIM; c++)
        P = __fmaf_rn(__ldg(zp + (size_t)c * 1024), __ldg(e + c), P);
    float t = __fsub_rn(A, __fmul_rn(2.0f, P));
    return __fadd_rn(t, C);
}

// One warp per row: exact argmin (first-index tie-break) over candidate set.
__global__ __launch_bounds__(256)
void rescore_kernel(const float* __restrict__ z, const float* __restrict__ emb) {
    const int wid = threadIdx.x >> 5, lane = threadIdx.x & 31;
    const int n = blockIdx.x * 8 + wid;
    const int b = n >> 10, hw = n & 1023;
    const float* zp = z + (size_t)b * CDIM * 1024 + hw;
    const float A = g_A[n];
    const int cnt = g_cnt[n];
    const float thresh = g_thresh[n];

    float bd = CUDART_INF_F;
    int bi = 0x7fffffff;

    if (cnt <= CAP) {
        for (int base = 0; base < cnt; base += 32) {
            int l = base + lane;
            if (l < cnt) {
                float s = g_cands[(size_t)n * CAP + l];
                if (s >= thresh) {
                    int k = (int)g_candk[(size_t)n * CAP + l];
                    float d = exact_d(zp, emb + (size_t)k * CDIM, A, g_C[k]);
                    if (d < bd || (d == bd && k < bi)) { bd = d; bi = k; }
                }
            }
        }
    } else {  // overflow fallback: exact scan of all codes (safety net)
        for (int k = lane; k < KCODES; k += 32) {
            float d = exact_d(zp, emb + (size_t)k * CDIM, A, g_C[k]);
            if (d < bd || (d == bd && k < bi)) { bd = d; bi = k; }
        }
    }
    #pragma unroll
    for (int off = 16; off; off >>= 1) {
        float od = __shfl_down_sync(0xffffffffu, bd, off);
        int   oi = __shfl_down_sync(0xffffffffu, bi, off);
        if (od < bd || (od == bd && oi < bi)) { bd = od; bi = oi; }
    }
    if (lane == 0) g_idx[n] = bi;
}

// ---------------------------------------------------------------------------
// Quantize / losses / indices (validated in R2)
// ---------------------------------------------------------------------------
__global__ __launch_bounds__(256)
void quantize_kernel(const float* __restrict__ z, const float* __restrict__ emb,
                     float* __restrict__ out) {
    __shared__ int bidx_s[64];
    __shared__ float red[256];
    const int tid = threadIdx.x;
    const int n0 = blockIdx.x * 64;
    const int bimg = n0 >> 10, hw0 = n0 & 1023;
    const float* zb = z + (size_t)bimg * CDIM * 1024 + hw0;
    const size_t QELEMS = (size_t)NROWS * CDIM;

    if (tid < 64) {
        int k = g_idx[n0 + tid];
        bidx_s[tid] = k;
        out[QELEMS + 2 + n0 + tid] = (float)k;
    }
    __syncthreads();

    float lsum = 0.f;
    for (int e = tid; e < 64 * CDIM; e += 256) {
        int c = e >> 6, m = e & 63;
        float q  = emb[(size_t)bidx_s[m] * CDIM + c];
        float zv = zb[(size_t)c * 1024 + m];
        float d  = __fsub_rn(q, zv);
        out[(size_t)bimg * CDIM * 1024 + (size_t)c * 1024 + hw0 + m] = __fadd_rn(zv, d);
        lsum = __fmaf_rn(d, d, lsum);
    }
    red[tid] = lsum;
    __syncthreads();
    #pragma unroll
    for (int st = 128; st; st >>= 1) {
        if (tid < st) red[tid] += red[tid + st];
        __syncthreads();
    }
    if (tid == 0) g_partial[blockIdx.x] = red[0];
}

__global__ void finalize_kernel(float* __restrict__ out) {
    __shared__ float red[256];
    red[threadIdx.x] = g_partial[threadIdx.x];
    __syncthreads();
    #pragma unroll
    for (int st = 128; st; st >>= 1) {
        if (threadIdx.x < st) red[threadIdx.x] += red[threadIdx.x + st];
        __syncthreads();
    }
    if (threadIdx.x == 0) {
        const size_t QELEMS = (size_t)NROWS * CDIM;
        float loss = red[0] / (float)QELEMS;
        out[QELEMS]     = loss;
        out[QELEMS + 1] = 0.25f * loss;
    }
}

// ---------------------------------------------------------------------------
extern "C" void kernel_launch(void* const* d_in, const int* in_sizes, int n_in,
                              void* d_out, int out_size) {
    const float* z   = (const float*)d_in[0];
    const float* emb = (const float*)d_in[1];
    float* out = (float*)d_out;

    cudaFuncSetAttribute(gemm_screen_kernel,
                         cudaFuncAttributeMaxDynamicSharedMemorySize, SM_TOTAL);

    conv_a_kernel<<<dim3(32, 8, 16), 256>>>(z);
    conv_b_kernel<<<KCODES * CDIM / 4 / 256, 256>>>(emb);
    c_kernel<<<KCODES / 128, 128>>>(emb);
    a_kernel<<<NROWS / 256, 256>>>(z);
    gemm_screen_kernel<<<NROWS / MT, GTHREADS, SM_TOTAL>>>();
    rescore_kernel<<<NROWS / 8, 256>>>(z, emb);
    quantize_kernel<<<NROWS / 64, 256>>>(z, emb, out);
    finalize_kernel<<<1, 256>>>(out);
}